// round 2
// baseline (speedup 1.0000x reference)
#include <cuda_runtime.h>

// out = feat @ Wv + bv
//
// The reference's softmax over axis=-2 (j) followed by einsum('ijk,ik->ik')
// (a sum over j) makes the attention-weight branch sum to exactly 1 per
// (i,k), so out[i,k] == v[i,k] == (feat @ Wv + bv)[i,k].
//
// feat: [N=1024, C=256] f32   (d_in[0])
// Wv:   [C, C]          f32   (d_in[9])
// bv:   [C]             f32   (d_in[10])
// out:  [N, C]          f32

namespace {

constexpr int Ndim = 1024;
constexpr int Cdim = 256;
constexpr int TM = 16;    // rows per block
constexpr int TN = 32;    // cols per block
constexpr int KC = 128;   // k-chunk
constexpr int PAD = 4;    // sA row stride = 132 floats -> bank (4*ty+k)%32, 16B aligned

__global__ __launch_bounds__(128, 8)
void vgemm_bias_kernel(const float* __restrict__ A,    // [N, C] feat
                       const float* __restrict__ B,    // [C, C] Wv
                       const float* __restrict__ bias, // [C]
                       float* __restrict__ O)          // [N, C]
{
    __shared__ float sA[TM][KC + PAD];  // 16 x 132 = 8.25 KB
    __shared__ float sB[KC][TN];        // 128 x 32 = 16 KB

    const int tid = threadIdx.x;     // 0..127
    const int tx  = tid & 7;         // 8 col groups of 4
    const int ty  = tid >> 3;        // 16 rows

    const int row0 = blockIdx.y * TM;
    const int col0 = blockIdx.x * TN;

    float acc0 = 0.f, acc1 = 0.f, acc2 = 0.f, acc3 = 0.f;

    #pragma unroll
    for (int kk = 0; kk < Cdim; kk += KC) {
        // --- load A tile: 16 rows x 128 k = 2048 floats = 512 float4; 4/thread
        #pragma unroll
        for (int i = 0; i < 4; i++) {
            const int idx = tid + i * 128;   // 0..511
            const int r   = idx >> 5;        // 32 float4 per row -> 16 rows
            const int c4  = idx & 31;
            float4 v = *reinterpret_cast<const float4*>(
                &A[(row0 + r) * Cdim + kk + c4 * 4]);
            *reinterpret_cast<float4*>(&sA[r][c4 * 4]) = v;
        }
        // --- load B tile: 128 k x 32 n = 4096 floats = 1024 float4; 8/thread
        #pragma unroll
        for (int i = 0; i < 8; i++) {
            const int idx = tid + i * 128;   // 0..1023
            const int r   = idx >> 3;        // 8 float4 per row -> 128 rows
            const int c4  = idx & 7;
            float4 v = *reinterpret_cast<const float4*>(
                &B[(kk + r) * Cdim + col0 + c4 * 4]);
            *reinterpret_cast<float4*>(&sB[r][c4 * 4]) = v;
        }
        __syncthreads();

        // --- 1x4 micro-tile over the k-chunk ---
        #pragma unroll 16
        for (int k = 0; k < KC; k++) {
            const float  a = sA[ty][k];
            const float4 b = *reinterpret_cast<const float4*>(&sB[k][tx * 4]);
            acc0 = fmaf(a, b.x, acc0);
            acc1 = fmaf(a, b.y, acc1);
            acc2 = fmaf(a, b.z, acc2);
            acc3 = fmaf(a, b.w, acc3);
        }
        __syncthreads();
    }

    // --- epilogue: bias add + float4 store ---
    const int col = col0 + tx * 4;
    const float4 bv4 = *reinterpret_cast<const float4*>(&bias[col]);
    float4 o;
    o.x = acc0 + bv4.x;
    o.y = acc1 + bv4.y;
    o.z = acc2 + bv4.z;
    o.w = acc3 + bv4.w;
    *reinterpret_cast<float4*>(&O[(row0 + ty) * Cdim + col]) = o;
}

} // namespace

extern "C" void kernel_launch(void* const* d_in, const int* in_sizes, int n_in,
                              void* d_out, int out_size)
{
    const float* feat = (const float*)d_in[0];
    const float* Wv   = (const float*)d_in[9];
    const float* bv   = (const float*)d_in[10];
    float* out        = (float*)d_out;

    dim3 grid(Cdim / TN, Ndim / TM);   // (8, 64) = 512 blocks
    dim3 block(128);
    vgemm_bias_kernel<<<grid, block>>>(feat, Wv, bv, out);
}

// round 4
// speedup vs baseline: 1.5507x; 1.5507x over previous
#include <cuda_runtime.h>

// out = feat @ Wv + bv
//
// The reference's softmax over axis=-2 (j) followed by einsum('ijk,ik->ik')
// (a sum over j) makes the attention-weight branch sum to exactly 1 per
// (i,k), so out[i,k] == v[i,k] == (feat @ Wv + bv)[i,k].
//
// feat: [N=1024, C=256] f32   (d_in[0])
// Wv:   [C, C]          f32   (d_in[9])
// bv:   [C]             f32   (d_in[10])
// out:  [N, C]          f32

namespace {

constexpr int Ndim = 1024;
constexpr int Cdim = 256;
constexpr int TM = 64;    // rows per block
constexpr int TN = 32;    // cols per block
constexpr int KC = 64;    // k-chunk (4 chunks, double-buffered)
constexpr int SAT_STRIDE = TM + 4;  // 68 floats = 272 B: 16B-aligned, bank-staggered

// 128 threads = 4 warps. Micro-tile 4x4: per k-iter just 2 LDS.128 + 16 FFMA,
// so the FFMA pipe (rt_SMSP=2 -> 32 cyc per k-iter) is the binding resource,
// not the smem crossbar (R2 failure mode). Grid = 128 blocks = 1/SM, one wave.

__global__ __launch_bounds__(128, 1)
void vgemm_bias_kernel(const float* __restrict__ A,    // [N, C] feat
                       const float* __restrict__ B,    // [C, C] Wv
                       const float* __restrict__ bias, // [C]
                       float* __restrict__ O)          // [N, C]
{
    __shared__ float sAT[2][KC][SAT_STRIDE];  // A tile, k-major (transposed)
    __shared__ float sB [2][KC][TN];          // B tile, k-major

    const int tid  = threadIdx.x;   // 0..127
    const int lane = tid & 31;
    const int warp = tid >> 5;
    const int tn   = tid & 7;       // col group (x4)
    const int tm   = tid >> 3;      // row group (x4), 0..15

    const int row0 = blockIdx.y * TM;
    const int col0 = blockIdx.x * TN;

    // ---- tile loaders ----
    // A: transpose during load. Unit u covers rows m0..m0+3 and 32 k's.
    // Global: 4 coalesced 128B rows; smem: one aligned, conflict-min STS.128.
    auto load_tiles = [&](int kk, int buf) {
        #pragma unroll
        for (int i = 0; i < 8; i++) {
            const int u  = warp * 8 + i;          // 0..31
            const int m0 = (u & 15) * 4;          // 0,4,...,60
            const int k  = ((u >> 4) << 5) + lane;// 0..63
            const float* gp = &A[(row0 + m0) * Cdim + kk + k];
            float4 v;
            v.x = gp[0 * Cdim];
            v.y = gp[1 * Cdim];
            v.z = gp[2 * Cdim];
            v.w = gp[3 * Cdim];
            *reinterpret_cast<float4*>(&sAT[buf][k][m0]) = v;
        }
        // B tile: 64 k x 32 n = 512 float4; 4 per thread, fully coalesced.
        #pragma unroll
        for (int i = 0; i < 4; i++) {
            const int idx = i * 128 + tid;   // 0..511
            const int r   = idx >> 3;        // 8 float4 per row
            const int c4  = (idx & 7) * 4;
            *reinterpret_cast<float4*>(&sB[buf][r][c4]) =
                *reinterpret_cast<const float4*>(&B[(kk + r) * Cdim + col0 + c4]);
        }
    };

    float acc[4][4];
    #pragma unroll
    for (int r = 0; r < 4; r++)
        #pragma unroll
        for (int c = 0; c < 4; c++) acc[r][c] = 0.f;

    load_tiles(0, 0);
    __syncthreads();

    #pragma unroll
    for (int chunk = 0; chunk < Cdim / KC; chunk++) {
        const int buf = chunk & 1;

        if (chunk + 1 < Cdim / KC)
            load_tiles((chunk + 1) * KC, buf ^ 1);

        #pragma unroll 8
        for (int k = 0; k < KC; k++) {
            const float4 a = *reinterpret_cast<const float4*>(&sAT[buf][k][tm * 4]);
            const float4 b = *reinterpret_cast<const float4*>(&sB [buf][k][tn * 4]);

            acc[0][0] = fmaf(a.x, b.x, acc[0][0]);
            acc[0][1] = fmaf(a.x, b.y, acc[0][1]);
            acc[0][2] = fmaf(a.x, b.z, acc[0][2]);
            acc[0][3] = fmaf(a.x, b.w, acc[0][3]);
            acc[1][0] = fmaf(a.y, b.x, acc[1][0]);
            acc[1][1] = fmaf(a.y, b.y, acc[1][1]);
            acc[1][2] = fmaf(a.y, b.z, acc[1][2]);
            acc[1][3] = fmaf(a.y, b.w, acc[1][3]);
            acc[2][0] = fmaf(a.z, b.x, acc[2][0]);
            acc[2][1] = fmaf(a.z, b.y, acc[2][1]);
            acc[2][2] = fmaf(a.z, b.z, acc[2][2]);
            acc[2][3] = fmaf(a.z, b.w, acc[2][3]);
            acc[3][0] = fmaf(a.w, b.x, acc[3][0]);
            acc[3][1] = fmaf(a.w, b.y, acc[3][1]);
            acc[3][2] = fmaf(a.w, b.z, acc[3][2]);
            acc[3][3] = fmaf(a.w, b.w, acc[3][3]);
        }
        __syncthreads();
    }

    // ---- epilogue: bias add + float4 stores ----
    const int col = col0 + tn * 4;
    const float4 bv4 = *reinterpret_cast<const float4*>(&bias[col]);
    #pragma unroll
    for (int r = 0; r < 4; r++) {
        const int row = row0 + tm * 4 + r;
        float4 o;
        o.x = acc[r][0] + bv4.x;
        o.y = acc[r][1] + bv4.y;
        o.z = acc[r][2] + bv4.z;
        o.w = acc[r][3] + bv4.w;
        *reinterpret_cast<float4*>(&O[row * Cdim + col]) = o;
    }
}

} // namespace

extern "C" void kernel_launch(void* const* d_in, const int* in_sizes, int n_in,
                              void* d_out, int out_size)
{
    const float* feat = (const float*)d_in[0];
    const float* Wv   = (const float*)d_in[9];
    const float* bv   = (const float*)d_in[10];
    float* out        = (float*)d_out;

    dim3 grid(Cdim / TN, Ndim / TM);   // (8, 16) = 128 blocks
    dim3 block(128);
    vgemm_bias_kernel<<<grid, block>>>(feat, Wv, bv, out);
}

// round 5
// speedup vs baseline: 1.5970x; 1.0299x over previous
#include <cuda_runtime.h>

// out = feat @ Wv + bv
//
// The reference's softmax over axis=-2 (j) followed by einsum('ijk,ik->ik')
// (a sum over j) makes the attention-weight branch sum to exactly 1 per
// (i,k), so out[i,k] == v[i,k] == (feat @ Wv + bv)[i,k].
//
// feat: [N=1024, C=256] f32   (d_in[0])
// Wv:   [C, C]          f32   (d_in[9])
// bv:   [C]             f32   (d_in[10])
// out:  [N, C]          f32

namespace {

constexpr int Ndim = 1024;
constexpr int Cdim = 256;
constexpr int TM = 64;    // rows per block
constexpr int TN = 32;    // cols per block
constexpr int KC = 64;    // k-chunk (4 chunks, double-buffered)
constexpr int SAT_STRIDE = TM + 4;  // 68 floats: 16B-aligned rows, bank-staggered

// 256 threads = 8 warps = 2 warps/SMSP. Micro-tile 4x2 (8 FFMA : 2 LDS per
// k-iter). Two warps per SMSP cut the per-warp issue duty needed to keep the
// FMA pipe full from 50% (R4's failure: measured 34%) to ~33%, hiding LDS
// latency and the double-buffer LDG bursts. Grid = 128 blocks, one wave.

__global__ __launch_bounds__(256, 1)
void vgemm_bias_kernel(const float* __restrict__ A,    // [N, C] feat
                       const float* __restrict__ B,    // [C, C] Wv
                       const float* __restrict__ bias, // [C]
                       float* __restrict__ O)          // [N, C]
{
    __shared__ float sAT[2][KC][SAT_STRIDE];  // A tile, k-major (transposed)
    __shared__ float sB [2][KC][TN];          // B tile, k-major

    const int tid  = threadIdx.x;   // 0..255
    const int lane = tid & 31;
    const int warp = tid >> 5;      // 0..7
    const int tn   = tid & 15;      // col group (x2), 0..15
    const int tm   = tid >> 4;      // row group (x4), 0..15

    const int row0 = blockIdx.y * TM;
    const int col0 = blockIdx.x * TN;

    // ---- tile loaders ----
    // A: transpose during load. 32 units; unit u covers rows m0..m0+3 and a
    // 32-wide k-slice. Global: 4 coalesced 128B row segments; smem: one
    // aligned STS.128 per lane.
    auto load_tiles = [&](int kk, int buf) {
        #pragma unroll
        for (int i = 0; i < 4; i++) {
            const int u  = warp * 4 + i;           // 0..31
            const int m0 = (u & 15) * 4;           // 0,4,...,60
            const int k  = ((u >> 4) << 5) + lane; // 0..63
            const float* gp = &A[(row0 + m0) * Cdim + kk + k];
            float4 v;
            v.x = gp[0 * Cdim];
            v.y = gp[1 * Cdim];
            v.z = gp[2 * Cdim];
            v.w = gp[3 * Cdim];
            *reinterpret_cast<float4*>(&sAT[buf][k][m0]) = v;
        }
        // B tile: 64 k x 32 n = 512 float4; 2 per thread, fully coalesced.
        #pragma unroll
        for (int i = 0; i < 2; i++) {
            const int idx = i * 256 + tid;   // 0..511
            const int r   = idx >> 3;        // 8 float4 per row
            const int c4  = (idx & 7) * 4;
            *reinterpret_cast<float4*>(&sB[buf][r][c4]) =
                *reinterpret_cast<const float4*>(&B[(kk + r) * Cdim + col0 + c4]);
        }
    };

    float acc[4][2];
    #pragma unroll
    for (int r = 0; r < 4; r++) {
        acc[r][0] = 0.f;
        acc[r][1] = 0.f;
    }

    load_tiles(0, 0);
    __syncthreads();

    #pragma unroll
    for (int chunk = 0; chunk < Cdim / KC; chunk++) {
        const int buf = chunk & 1;

        if (chunk + 1 < Cdim / KC)
            load_tiles((chunk + 1) * KC, buf ^ 1);

        #pragma unroll 16
        for (int k = 0; k < KC; k++) {
            const float4 a = *reinterpret_cast<const float4*>(&sAT[buf][k][tm * 4]);
            const float2 b = *reinterpret_cast<const float2*>(&sB [buf][k][tn * 2]);

            acc[0][0] = fmaf(a.x, b.x, acc[0][0]);
            acc[0][1] = fmaf(a.x, b.y, acc[0][1]);
            acc[1][0] = fmaf(a.y, b.x, acc[1][0]);
            acc[1][1] = fmaf(a.y, b.y, acc[1][1]);
            acc[2][0] = fmaf(a.z, b.x, acc[2][0]);
            acc[2][1] = fmaf(a.z, b.y, acc[2][1]);
            acc[3][0] = fmaf(a.w, b.x, acc[3][0]);
            acc[3][1] = fmaf(a.w, b.y, acc[3][1]);
        }
        __syncthreads();
    }

    // ---- epilogue: bias add + float2 stores ----
    const int col = col0 + tn * 2;
    const float2 bv2 = *reinterpret_cast<const float2*>(&bias[col]);
    #pragma unroll
    for (int r = 0; r < 4; r++) {
        const int row = row0 + tm * 4 + r;
        float2 o;
        o.x = acc[r][0] + bv2.x;
        o.y = acc[r][1] + bv2.y;
        *reinterpret_cast<float2*>(&O[row * Cdim + col]) = o;
    }
}

} // namespace

extern "C" void kernel_launch(void* const* d_in, const int* in_sizes, int n_in,
                              void* d_out, int out_size)
{
    const float* feat = (const float*)d_in[0];
    const float* Wv   = (const float*)d_in[9];
    const float* bv   = (const float*)d_in[10];
    float* out        = (float*)d_out;

    dim3 grid(Cdim / TN, Ndim / TM);   // (8, 16) = 128 blocks
    dim3 block(256);
    vgemm_bias_kernel<<<grid, block>>>(feat, Wv, bv, out);
}